// round 15
// baseline (speedup 1.0000x reference)
#include <cuda_runtime.h>
#include <cuda_bf16.h>
#include <cstdint>

#define NN   100000
#define NE   1600000
#define FIN  128
#define D    64
#define NCENT 100
#define NPAD  104
#define NCLS  10
#define EPSV 1e-12f
#define NSCANBLK 98

// ---------------- device scratch (no allocation allowed) ----------------
__device__ float           g_h[NN * D];          // fp32 post-aggregation activations
__device__ __nv_bfloat162  g_hwb[NN * D / 2];    // bf16 prescaled hw: dinv[n]*hw[n][:]
__device__ float g_dinv[NN];
__device__ int   g_deg[NN];
__device__ int   g_rs[NN + 1];
__device__ int   g_csr[NE];
__device__ int   g_erank[NE];    // rank of edge within its dst bucket (-1 invalid)
__device__ int   g_bsum[128];
__device__ int   g_boff[128];
__device__ float g_M[D * FIN];
__device__ float g_pooled[NCENT];
__device__ int   g_is64;
__device__ unsigned g_ticket;    // last-block ticket for distpool->out fold

// ---------------- init: zero deg/pooled/ticket + dtype detect + computeM ----
// (k_computeM folded in: blocks 0..31 also compute M = W_gcn[0] @ W_embed)
__global__ void k_init(const int* __restrict__ w,
                       const float* __restrict__ W0, const float* __restrict__ We) {
    int i = blockIdx.x * blockDim.x + threadIdx.x;
    if (i < NN) g_deg[i] = 0;
    if (i < NCENT) g_pooled[i] = 0.f;
    if (i == 0) {
        g_ticket = 0u;
        int nz = 0;
        for (int j = 0; j < 64; j++) nz += (w[2 * j + 1] != 0);
        g_is64 = (nz == 0) ? 1 : 0;
    }
    if (i < D * FIN) {
        int r = i / FIN, c = i % FIN;
        float s = 0.f;
        #pragma unroll
        for (int k = 0; k < D; k++) s += W0[r * D + k] * We[k * FIN + c];
        g_M[i] = s;
    }
}

__device__ __forceinline__ int load_idx(const int* w, unsigned pos) {
    return g_is64 ? w[2u * pos] : w[pos];   // little-endian low word == value
}

// degree count + per-edge rank capture (atomic return value)
__global__ void k_degree(const int* __restrict__ w) {
    unsigned e = blockIdx.x * blockDim.x + threadIdx.x;
    if (e < NE) {
        int src = load_idx(w, e);
        int dst = load_idx(w, (unsigned)NE + e);
        int rank = -1;
        if ((unsigned)dst < NN && (unsigned)src < NN)
            rank = atomicAdd(&g_deg[dst], 1);
        g_erank[e] = rank;
    }
}

// ---------------- exclusive scan of g_deg -> g_rs (+ dinv fused) ----------
__global__ void k_scan1() {
    __shared__ int s[1024];
    int t = threadIdx.x;
    int gid = blockIdx.x * 1024 + t;
    int v = (gid < NN) ? g_deg[gid] : 0;
    if (gid < NN) g_dinv[gid] = rsqrtf((float)(v + 1));   // fused: +1 self loop
    s[t] = v;
    __syncthreads();
    for (int off = 1; off < 1024; off <<= 1) {
        int x = (t >= off) ? s[t - off] : 0;
        __syncthreads();
        s[t] += x;
        __syncthreads();
    }
    if (gid < NN) g_rs[gid] = s[t] - v;    // exclusive within block
    if (t == 1023) g_bsum[blockIdx.x] = s[1023];
}

// parallel scan over block sums (nblk <= 128)
__global__ void k_scan2(int nblk) {
    __shared__ int s[128];
    int t = threadIdx.x;
    int v = (t < nblk) ? g_bsum[t] : 0;
    s[t] = v;
    __syncthreads();
    for (int off = 1; off < 128; off <<= 1) {
        int x = (t >= off) ? s[t - off] : 0;
        __syncthreads();
        s[t] += x;
        __syncthreads();
    }
    if (t < nblk) g_boff[t] = s[t] - v;    // exclusive
}

__global__ void k_scan3() {
    int t = threadIdx.x;
    int gid = blockIdx.x * 1024 + t;
    if (gid < NN) g_rs[gid] += g_boff[blockIdx.x];
}

// atomic-free CSR fill: slot = rs[dst] + rank (src/dst re-decoded, L2-warm)
__global__ void k_fill_csr(const int* __restrict__ w) {
    unsigned e = blockIdx.x * blockDim.x + threadIdx.x;
    if (e < NE) {
        int rank = g_erank[e];
        if (rank >= 0) {
            int src = load_idx(w, e);
            int dst = load_idx(w, (unsigned)NE + e);
            g_csr[g_rs[dst] + rank] = src;
        }
    }
}

// ---------------- tf32 tensor-core GEMM, epilogue: prescale by dinv, store bf16
// out_bf16[n][c] = dinv[n] * sum_k A[n][k]*W[c][k]
template <int KTOT>
__device__ __forceinline__ void gemm_tc_body(const float* __restrict__ A,
                                             const float* __restrict__ W) {
    __shared__ uint32_t sA[64][68];
    __shared__ uint32_t sW[64][68];
    int t = threadIdx.x;
    int warp = t >> 5, lane = t & 31;
    int grp = lane >> 2, tig = lane & 3;
    int rowBase = blockIdx.x * 64 + warp * 16;

    float c[8][4];
    #pragma unroll
    for (int nt = 0; nt < 8; nt++)
        #pragma unroll
        for (int j = 0; j < 4; j++) c[nt][j] = 0.f;

    for (int kc = 0; kc < KTOT; kc += 64) {
        for (int i = t; i < 4096; i += 128) {
            int r = i >> 6, k = i & 63;
            int gn = blockIdx.x * 64 + r;
            float av = (gn < NN) ? A[(long long)gn * KTOT + kc + k] : 0.f;
            float wv = W[r * KTOT + kc + k];
            uint32_t ai, wi;
            asm("cvt.rna.tf32.f32 %0, %1;" : "=r"(ai) : "f"(av));
            asm("cvt.rna.tf32.f32 %0, %1;" : "=r"(wi) : "f"(wv));
            sA[r][k] = ai;
            sW[r][k] = wi;
        }
        __syncthreads();
        #pragma unroll
        for (int k0 = 0; k0 < 64; k0 += 8) {
            uint32_t a0 = sA[warp * 16 + grp][k0 + tig];
            uint32_t a1 = sA[warp * 16 + grp + 8][k0 + tig];
            uint32_t a2 = sA[warp * 16 + grp][k0 + tig + 4];
            uint32_t a3 = sA[warp * 16 + grp + 8][k0 + tig + 4];
            #pragma unroll
            for (int nt = 0; nt < 8; nt++) {
                uint32_t b0 = sW[nt * 8 + grp][k0 + tig];
                uint32_t b1 = sW[nt * 8 + grp][k0 + tig + 4];
                asm volatile(
                    "mma.sync.aligned.m16n8k8.row.col.f32.tf32.tf32.f32 "
                    "{%0,%1,%2,%3}, {%4,%5,%6,%7}, {%8,%9}, {%0,%1,%2,%3};"
                    : "+f"(c[nt][0]), "+f"(c[nt][1]), "+f"(c[nt][2]), "+f"(c[nt][3])
                    : "r"(a0), "r"(a1), "r"(a2), "r"(a3), "r"(b0), "r"(b1));
            }
        }
        __syncthreads();
    }
    int r0 = rowBase + grp;
    int r1 = rowBase + grp + 8;
    float d0 = (r0 < NN) ? g_dinv[r0] : 0.f;
    float d1 = (r1 < NN) ? g_dinv[r1] : 0.f;
    #pragma unroll
    for (int nt = 0; nt < 8; nt++) {
        int colh = nt * 4 + tig;            // bf162 index (= col/2)
        if (r0 < NN)
            g_hwb[(long long)r0 * 32 + colh] = __floats2bfloat162_rn(c[nt][0] * d0, c[nt][1] * d0);
        if (r1 < NN)
            g_hwb[(long long)r1 * 32 + colh] = __floats2bfloat162_rn(c[nt][2] * d1, c[nt][3] * d1);
    }
}

__global__ __launch_bounds__(128) void k_gemm0_tc(const float* __restrict__ x) {
    gemm_tc_body<FIN>(x, g_M);
}
__global__ __launch_bounds__(128) void k_gemm12_tc(const float* __restrict__ W) {
    gemm_tc_body<D>(g_h, W);
}

// ---------------- CSR aggregation: TWO nodes per warp, uint2 cg-gathers ----
// half-warp (16 lanes) per node; lane handles 4 features via one LDG.64.
// __ldcg: random gathers across 12.8MB have ~2% L1 hit rate — bypass L1 to
// cut L1tex replay overhead; data is fully L2-resident.
// h[i] = relu( dinv[i] * (sum_src hws[src] + hws[i]) + b ),  hws = dinv*hw
__global__ __launch_bounds__(256) void k_aggregate(const float* __restrict__ bias) {
    int warpId = (blockIdx.x * blockDim.x + threadIdx.x) >> 5;
    int lane = threadIdx.x & 31;
    unsigned fl = lane & 15;               // feature-lane: features 4*fl .. 4*fl+3
    int node = warpId * 2 + (lane >> 4);   // half-warp -> node
    if (node >= NN) return;                // NN even: whole warp uniform

    int s0 = g_rs[node];
    int deg = g_deg[node];
    int mdeg = max(deg, __shfl_xor_sync(0xFFFFFFFFu, deg, 16));  // warp-uniform

    const uint2* hwb2 = reinterpret_cast<const uint2*>(g_hwb);   // row = 16 uint2
    float a0 = 0.f, a1 = 0.f, a2 = 0.f, a3 = 0.f;
    for (int j = 0; j < mdeg; j += 4) {
        bool v0 = j < deg, v1 = j + 1 < deg, v2 = j + 2 < deg, v3 = j + 3 < deg;
        int i0 = v0 ? g_csr[s0 + j]     : node;
        int i1 = v1 ? g_csr[s0 + j + 1] : node;
        int i2 = v2 ? g_csr[s0 + j + 2] : node;
        int i3 = v3 ? g_csr[s0 + j + 3] : node;
        uint2 u0 = __ldcg(&hwb2[(unsigned)i0 * 16u + fl]);
        uint2 u1 = __ldcg(&hwb2[(unsigned)i1 * 16u + fl]);
        uint2 u2 = __ldcg(&hwb2[(unsigned)i2 * 16u + fl]);
        uint2 u3 = __ldcg(&hwb2[(unsigned)i3 * 16u + fl]);
        if (v0) {
            float2 p = __bfloat1622float2(*reinterpret_cast<__nv_bfloat162*>(&u0.x));
            float2 q = __bfloat1622float2(*reinterpret_cast<__nv_bfloat162*>(&u0.y));
            a0 += p.x; a1 += p.y; a2 += q.x; a3 += q.y;
        }
        if (v1) {
            float2 p = __bfloat1622float2(*reinterpret_cast<__nv_bfloat162*>(&u1.x));
            float2 q = __bfloat1622float2(*reinterpret_cast<__nv_bfloat162*>(&u1.y));
            a0 += p.x; a1 += p.y; a2 += q.x; a3 += q.y;
        }
        if (v2) {
            float2 p = __bfloat1622float2(*reinterpret_cast<__nv_bfloat162*>(&u2.x));
            float2 q = __bfloat1622float2(*reinterpret_cast<__nv_bfloat162*>(&u2.y));
            a0 += p.x; a1 += p.y; a2 += q.x; a3 += q.y;
        }
        if (v3) {
            float2 p = __bfloat1622float2(*reinterpret_cast<__nv_bfloat162*>(&u3.x));
            float2 q = __bfloat1622float2(*reinterpret_cast<__nv_bfloat162*>(&u3.y));
            a0 += p.x; a1 += p.y; a2 += q.x; a3 += q.y;
        }
    }
    // self term + bias + relu
    uint2 us = hwb2[(unsigned)node * 16u + fl];
    float2 ps = __bfloat1622float2(*reinterpret_cast<__nv_bfloat162*>(&us.x));
    float2 qs = __bfloat1622float2(*reinterpret_cast<__nv_bfloat162*>(&us.y));
    float di = g_dinv[node];
    float4 bb = reinterpret_cast<const float4*>(bias)[fl];
    float4 r;
    r.x = fmaxf(di * (a0 + ps.x) + bb.x, 0.f);
    r.y = fmaxf(di * (a1 + ps.y) + bb.y, 0.f);
    r.z = fmaxf(di * (a2 + qs.x) + bb.z, 0.f);
    r.w = fmaxf(di * (a3 + qs.y) + bb.w, 0.f);
    reinterpret_cast<float4*>(g_h)[(unsigned)node * 16u + fl] = r;
}

// ---------------- tensor-core centroid distance + mean pooling + head ----
// per block: 64 node rows x NPAD centroid cols via tf32 mma m16n8k8.
// Last block (atomic ticket) computes the final linear head (k_out folded).
__global__ __launch_bounds__(128) void k_distpool_tc(const float* __restrict__ cent,
                                                     const float* __restrict__ Wout,
                                                     const float* __restrict__ bout,
                                                     float* __restrict__ out) {
    __shared__ uint32_t sH[64][68];
    __shared__ uint32_t sCt[NPAD][68];
    __shared__ float sh2[64];
    __shared__ float sc2[NPAD];
    __shared__ float sPool[NPAD];
    __shared__ unsigned sTicket;
    int t = threadIdx.x;
    int warp = t >> 5, lane = t & 31;
    int grp = lane >> 2, tig = lane & 3;
    int base = blockIdx.x * 64;

    for (int i = t; i < NPAD * 64; i += 128) {
        int col = i >> 6, k = i & 63;
        float v = (col < NCENT) ? cent[col * 64 + k] : 0.f;
        uint32_t b;
        asm("cvt.rna.tf32.f32 %0, %1;" : "=r"(b) : "f"(v));
        sCt[col][k] = b;
    }
    for (int i = t; i < 4096; i += 128) {
        int r = i >> 6, k = i & 63;
        int gn = base + r;
        float v = (gn < NN) ? g_h[(long long)gn * D + k] : 0.f;
        uint32_t b;
        asm("cvt.rna.tf32.f32 %0, %1;" : "=r"(b) : "f"(v));
        sH[r][k] = b;
    }
    if (t < NPAD) sPool[t] = 0.f;
    __syncthreads();

    // per-row |h|^2 (two threads per row)
    {
        int r = t >> 1, half = t & 1;
        float s = 0.f;
        #pragma unroll
        for (int k = 0; k < 32; k++) {
            float x = __uint_as_float(sH[r][half * 32 + k]);
            s += x * x;
        }
        s += __shfl_xor_sync(0xFFFFFFFFu, s, 1);
        if (half == 0) sh2[r] = s;
    }
    if (t < NPAD) {
        float s = 0.f;
        #pragma unroll
        for (int k = 0; k < D; k++) {
            float x = __uint_as_float(sCt[t][k]);
            s += x * x;
        }
        sc2[t] = s;
    }
    __syncthreads();

    float c[13][4];
    #pragma unroll
    for (int nt = 0; nt < 13; nt++)
        #pragma unroll
        for (int j = 0; j < 4; j++) c[nt][j] = 0.f;

    int rowS = warp * 16;
    #pragma unroll
    for (int k0 = 0; k0 < 64; k0 += 8) {
        uint32_t a0 = sH[rowS + grp][k0 + tig];
        uint32_t a1 = sH[rowS + grp + 8][k0 + tig];
        uint32_t a2 = sH[rowS + grp][k0 + tig + 4];
        uint32_t a3 = sH[rowS + grp + 8][k0 + tig + 4];
        #pragma unroll
        for (int nt = 0; nt < 13; nt++) {
            uint32_t b0 = sCt[nt * 8 + grp][k0 + tig];
            uint32_t b1 = sCt[nt * 8 + grp][k0 + tig + 4];
            asm volatile(
                "mma.sync.aligned.m16n8k8.row.col.f32.tf32.tf32.f32 "
                "{%0,%1,%2,%3}, {%4,%5,%6,%7}, {%8,%9}, {%0,%1,%2,%3};"
                : "+f"(c[nt][0]), "+f"(c[nt][1]), "+f"(c[nt][2]), "+f"(c[nt][3])
                : "r"(a0), "r"(a1), "r"(a2), "r"(a3), "r"(b0), "r"(b1));
        }
    }

    int lr0 = rowS + grp, lr1 = lr0 + 8;
    int gr0 = base + lr0, gr1 = base + lr1;
    float h20 = sh2[lr0], h21 = sh2[lr1];
    #pragma unroll
    for (int nt = 0; nt < 13; nt++) {
        int col0 = nt * 8 + tig * 2;
        int col1 = col0 + 1;
        float c20 = sc2[col0], c21 = sc2[col1];
        float d00 = fmaxf(h20 + c20 - 2.f * c[nt][0], 0.f) + EPSV;
        float d01 = fmaxf(h20 + c21 - 2.f * c[nt][1], 0.f) + EPSV;
        float d10 = fmaxf(h21 + c20 - 2.f * c[nt][2], 0.f) + EPSV;
        float d11 = fmaxf(h21 + c21 - 2.f * c[nt][3], 0.f) + EPSV;
        float q00, q01, q10, q11;
        asm("sqrt.approx.f32 %0, %1;" : "=f"(q00) : "f"(d00));
        asm("sqrt.approx.f32 %0, %1;" : "=f"(q01) : "f"(d01));
        asm("sqrt.approx.f32 %0, %1;" : "=f"(q10) : "f"(d10));
        asm("sqrt.approx.f32 %0, %1;" : "=f"(q11) : "f"(d11));
        float s0 = ((gr0 < NN) ? q00 : 0.f) + ((gr1 < NN) ? q10 : 0.f);
        float s1 = ((gr0 < NN) ? q01 : 0.f) + ((gr1 < NN) ? q11 : 0.f);
        #pragma unroll
        for (int m = 4; m < 32; m <<= 1) {
            s0 += __shfl_xor_sync(0xFFFFFFFFu, s0, m);
            s1 += __shfl_xor_sync(0xFFFFFFFFu, s1, m);
        }
        if (lane < 4) {
            if (col0 < NCENT) atomicAdd(&sPool[col0], s0);
            if (col1 < NCENT) atomicAdd(&sPool[col1], s1);
        }
    }
    __syncthreads();
    if (t < NCENT) atomicAdd(&g_pooled[t], sPool[t]);

    // ---- last-block: compute final head (replaces k_out launch) ----
    __threadfence();
    __syncthreads();
    if (t == 0) sTicket = atomicAdd(&g_ticket, 1u);
    __syncthreads();
    if (sTicket == gridDim.x - 1) {
        if (t < NCLS) {
            const float invN = 1.0f / (float)NN;
            float s = 0.f;
            #pragma unroll
            for (int k = 0; k < NCENT; k++) {
                float pv = __ldcg(&g_pooled[k]);   // L2 read: fresh after fences
                s += (pv * invN) * Wout[t * NCENT + k];
            }
            out[t] = s + bout[t];
        }
    }
}

// ---------------- launch ----------------
extern "C" void kernel_launch(void* const* d_in, const int* in_sizes, int n_in,
                              void* d_out, int out_size) {
    const float* x    = (const float*)d_in[0];
    const int*   eiw  = (const int*)d_in[1];     // raw words; dtype detected on device
    const float* We   = (const float*)d_in[2];
    const float* Wg   = (const float*)d_in[3];   // [3,64,64]
    const float* bg   = (const float*)d_in[4];   // [3,64]
    const float* cent = (const float*)d_in[5];   // [100,64]
    const float* Wout = (const float*)d_in[6];   // [10,100]
    const float* bout = (const float*)d_in[7];   // [10]
    float*       out  = (float*)d_out;

    const int edgeBlk  = (NE + 255) / 256;             // 6250
    const int nodeBlk  = (NN + 255) / 256;             // 391
    const int gemmBlk  = (NN + 63) / 64;               // 1563
    const int aggBlk   = (NN / 2 * 32 + 255) / 256;    // 6250 (2 nodes/warp)

    // init (+computeM fused) + CSR/norm build
    k_init<<<nodeBlk, 256>>>(eiw, Wg, We);
    k_degree<<<edgeBlk, 256>>>(eiw);
    k_scan1<<<NSCANBLK, 1024>>>();
    k_scan2<<<1, 128>>>(NSCANBLK);
    k_scan3<<<NSCANBLK, 1024>>>();
    k_fill_csr<<<edgeBlk, 256>>>(eiw);

    // layer 0 (fused): hws = dinv * (x @ M^T)   (tf32 tensor cores, bf16 store)
    k_gemm0_tc<<<gemmBlk, 128>>>(x);
    k_aggregate<<<aggBlk, 256>>>(bg + 0 * D);

    // layer 1
    k_gemm12_tc<<<gemmBlk, 128>>>(Wg + 1 * D * D);
    k_aggregate<<<aggBlk, 256>>>(bg + 1 * D);

    // layer 2
    k_gemm12_tc<<<gemmBlk, 128>>>(Wg + 2 * D * D);
    k_aggregate<<<aggBlk, 256>>>(bg + 2 * D);

    // distance + pooling + head (tensor cores; k_out folded via last-block)
    k_distpool_tc<<<gemmBlk, 128>>>(cent, Wout, bout, out);
}

// round 17
// speedup vs baseline: 1.0285x; 1.0285x over previous
#include <cuda_runtime.h>
#include <cuda_bf16.h>
#include <cstdint>

#define NN   100000
#define NE   1600000
#define FIN  128
#define D    64
#define NCENT 100
#define NPAD  104
#define NCLS  10
#define EPSV 1e-12f
#define NSCANBLK 98

// ---------------- device scratch (no allocation allowed) ----------------
__device__ float           g_h[NN * D];          // fp32 post-aggregation activations
__device__ __nv_bfloat162  g_hwb[NN * D / 2];    // bf16 prescaled hw: dinv[n]*hw[n][:]
__device__ float g_dinv[NN];
__device__ int   g_deg[NN];
__device__ int   g_rs[NN + 1];
__device__ int   g_csr[NE];
__device__ int   g_erank[NE];    // rank of edge within its dst bucket (-1 invalid)
__device__ int   g_bsum[128];
__device__ int   g_boff[128];
__device__ float g_M[D * FIN];
__device__ float g_pooled[NCENT];
__device__ int   g_is64;
__device__ unsigned g_ticket;    // last-block ticket for distpool->out fold

// ---------------- init: zero deg/pooled/ticket + dtype detect + computeM ----
// (k_computeM folded in: blocks 0..31 also compute M = W_gcn[0] @ W_embed)
__global__ void k_init(const int* __restrict__ w,
                       const float* __restrict__ W0, const float* __restrict__ We) {
    int i = blockIdx.x * blockDim.x + threadIdx.x;
    if (i < NN) g_deg[i] = 0;
    if (i < NCENT) g_pooled[i] = 0.f;
    if (i == 0) {
        g_ticket = 0u;
        int nz = 0;
        for (int j = 0; j < 64; j++) nz += (w[2 * j + 1] != 0);
        g_is64 = (nz == 0) ? 1 : 0;
    }
    if (i < D * FIN) {
        int r = i / FIN, c = i % FIN;
        float s = 0.f;
        #pragma unroll
        for (int k = 0; k < D; k++) s += W0[r * D + k] * We[k * FIN + c];
        g_M[i] = s;
    }
}

__device__ __forceinline__ int load_idx(const int* w, unsigned pos) {
    return g_is64 ? w[2u * pos] : w[pos];   // little-endian low word == value
}

// degree count + per-edge rank capture (atomic return value)
__global__ void k_degree(const int* __restrict__ w) {
    unsigned e = blockIdx.x * blockDim.x + threadIdx.x;
    if (e < NE) {
        int src = load_idx(w, e);
        int dst = load_idx(w, (unsigned)NE + e);
        int rank = -1;
        if ((unsigned)dst < NN && (unsigned)src < NN)
            rank = atomicAdd(&g_deg[dst], 1);
        g_erank[e] = rank;
    }
}

// ---------------- exclusive scan of g_deg -> g_rs (+ dinv fused) ----------
__global__ void k_scan1() {
    __shared__ int s[1024];
    int t = threadIdx.x;
    int gid = blockIdx.x * 1024 + t;
    int v = (gid < NN) ? g_deg[gid] : 0;
    if (gid < NN) g_dinv[gid] = rsqrtf((float)(v + 1));   // fused: +1 self loop
    s[t] = v;
    __syncthreads();
    for (int off = 1; off < 1024; off <<= 1) {
        int x = (t >= off) ? s[t - off] : 0;
        __syncthreads();
        s[t] += x;
        __syncthreads();
    }
    if (gid < NN) g_rs[gid] = s[t] - v;    // exclusive within block
    if (t == 1023) g_bsum[blockIdx.x] = s[1023];
}

// parallel scan over block sums (nblk <= 128)
__global__ void k_scan2(int nblk) {
    __shared__ int s[128];
    int t = threadIdx.x;
    int v = (t < nblk) ? g_bsum[t] : 0;
    s[t] = v;
    __syncthreads();
    for (int off = 1; off < 128; off <<= 1) {
        int x = (t >= off) ? s[t - off] : 0;
        __syncthreads();
        s[t] += x;
        __syncthreads();
    }
    if (t < nblk) g_boff[t] = s[t] - v;    // exclusive
}

__global__ void k_scan3() {
    int t = threadIdx.x;
    int gid = blockIdx.x * 1024 + t;
    if (gid < NN) g_rs[gid] += g_boff[blockIdx.x];
}

// atomic-free CSR fill: slot = rs[dst] + rank (src/dst re-decoded, L2-warm)
__global__ void k_fill_csr(const int* __restrict__ w) {
    unsigned e = blockIdx.x * blockDim.x + threadIdx.x;
    if (e < NE) {
        int rank = g_erank[e];
        if (rank >= 0) {
            int src = load_idx(w, e);
            int dst = load_idx(w, (unsigned)NE + e);
            g_csr[g_rs[dst] + rank] = src;
        }
    }
}

// ---------------- tf32 tensor-core GEMM, epilogue: prescale by dinv, store bf16
// out_bf16[n][c] = dinv[n] * sum_k A[n][k]*W[c][k]
template <int KTOT>
__device__ __forceinline__ void gemm_tc_body(const float* __restrict__ A,
                                             const float* __restrict__ W) {
    __shared__ uint32_t sA[64][68];
    __shared__ uint32_t sW[64][68];
    int t = threadIdx.x;
    int warp = t >> 5, lane = t & 31;
    int grp = lane >> 2, tig = lane & 3;
    int rowBase = blockIdx.x * 64 + warp * 16;

    float c[8][4];
    #pragma unroll
    for (int nt = 0; nt < 8; nt++)
        #pragma unroll
        for (int j = 0; j < 4; j++) c[nt][j] = 0.f;

    for (int kc = 0; kc < KTOT; kc += 64) {
        for (int i = t; i < 4096; i += 128) {
            int r = i >> 6, k = i & 63;
            int gn = blockIdx.x * 64 + r;
            float av = (gn < NN) ? A[(long long)gn * KTOT + kc + k] : 0.f;
            float wv = W[r * KTOT + kc + k];
            uint32_t ai, wi;
            asm("cvt.rna.tf32.f32 %0, %1;" : "=r"(ai) : "f"(av));
            asm("cvt.rna.tf32.f32 %0, %1;" : "=r"(wi) : "f"(wv));
            sA[r][k] = ai;
            sW[r][k] = wi;
        }
        __syncthreads();
        #pragma unroll
        for (int k0 = 0; k0 < 64; k0 += 8) {
            uint32_t a0 = sA[warp * 16 + grp][k0 + tig];
            uint32_t a1 = sA[warp * 16 + grp + 8][k0 + tig];
            uint32_t a2 = sA[warp * 16 + grp][k0 + tig + 4];
            uint32_t a3 = sA[warp * 16 + grp + 8][k0 + tig + 4];
            #pragma unroll
            for (int nt = 0; nt < 8; nt++) {
                uint32_t b0 = sW[nt * 8 + grp][k0 + tig];
                uint32_t b1 = sW[nt * 8 + grp][k0 + tig + 4];
                asm volatile(
                    "mma.sync.aligned.m16n8k8.row.col.f32.tf32.tf32.f32 "
                    "{%0,%1,%2,%3}, {%4,%5,%6,%7}, {%8,%9}, {%0,%1,%2,%3};"
                    : "+f"(c[nt][0]), "+f"(c[nt][1]), "+f"(c[nt][2]), "+f"(c[nt][3])
                    : "r"(a0), "r"(a1), "r"(a2), "r"(a3), "r"(b0), "r"(b1));
            }
        }
        __syncthreads();
    }
    int r0 = rowBase + grp;
    int r1 = rowBase + grp + 8;
    float d0 = (r0 < NN) ? g_dinv[r0] : 0.f;
    float d1 = (r1 < NN) ? g_dinv[r1] : 0.f;
    #pragma unroll
    for (int nt = 0; nt < 8; nt++) {
        int colh = nt * 4 + tig;            // bf162 index (= col/2)
        if (r0 < NN)
            g_hwb[(long long)r0 * 32 + colh] = __floats2bfloat162_rn(c[nt][0] * d0, c[nt][1] * d0);
        if (r1 < NN)
            g_hwb[(long long)r1 * 32 + colh] = __floats2bfloat162_rn(c[nt][2] * d1, c[nt][3] * d1);
    }
}

__global__ __launch_bounds__(128) void k_gemm0_tc(const float* __restrict__ x) {
    gemm_tc_body<FIN>(x, g_M);
}
__global__ __launch_bounds__(128) void k_gemm12_tc(const float* __restrict__ W) {
    gemm_tc_body<D>(g_h, W);
}

// ---------------- CSR aggregation: TWO nodes per warp, uint2 gathers ----
// half-warp (16 lanes) per node; lane handles 4 features via one LDG.64.
// __ldg (L1-cached): per-SM temporal reuse is real — aggregate L1 (33MB)
// exceeds the 12.8MB working set; R15's __ldcg bypass regressed +6us.
// h[i] = relu( dinv[i] * (sum_src hws[src] + hws[i]) + b ),  hws = dinv*hw
__global__ __launch_bounds__(256) void k_aggregate(const float* __restrict__ bias) {
    int warpId = (blockIdx.x * blockDim.x + threadIdx.x) >> 5;
    int lane = threadIdx.x & 31;
    unsigned fl = lane & 15;               // feature-lane: features 4*fl .. 4*fl+3
    int node = warpId * 2 + (lane >> 4);   // half-warp -> node
    if (node >= NN) return;                // NN even: whole warp uniform

    int s0 = g_rs[node];
    int deg = g_deg[node];
    int mdeg = max(deg, __shfl_xor_sync(0xFFFFFFFFu, deg, 16));  // warp-uniform

    const uint2* hwb2 = reinterpret_cast<const uint2*>(g_hwb);   // row = 16 uint2
    float a0 = 0.f, a1 = 0.f, a2 = 0.f, a3 = 0.f;
    for (int j = 0; j < mdeg; j += 4) {
        bool v0 = j < deg, v1 = j + 1 < deg, v2 = j + 2 < deg, v3 = j + 3 < deg;
        int i0 = v0 ? g_csr[s0 + j]     : node;
        int i1 = v1 ? g_csr[s0 + j + 1] : node;
        int i2 = v2 ? g_csr[s0 + j + 2] : node;
        int i3 = v3 ? g_csr[s0 + j + 3] : node;
        uint2 u0 = __ldg(&hwb2[(unsigned)i0 * 16u + fl]);
        uint2 u1 = __ldg(&hwb2[(unsigned)i1 * 16u + fl]);
        uint2 u2 = __ldg(&hwb2[(unsigned)i2 * 16u + fl]);
        uint2 u3 = __ldg(&hwb2[(unsigned)i3 * 16u + fl]);
        if (v0) {
            float2 p = __bfloat1622float2(*reinterpret_cast<__nv_bfloat162*>(&u0.x));
            float2 q = __bfloat1622float2(*reinterpret_cast<__nv_bfloat162*>(&u0.y));
            a0 += p.x; a1 += p.y; a2 += q.x; a3 += q.y;
        }
        if (v1) {
            float2 p = __bfloat1622float2(*reinterpret_cast<__nv_bfloat162*>(&u1.x));
            float2 q = __bfloat1622float2(*reinterpret_cast<__nv_bfloat162*>(&u1.y));
            a0 += p.x; a1 += p.y; a2 += q.x; a3 += q.y;
        }
        if (v2) {
            float2 p = __bfloat1622float2(*reinterpret_cast<__nv_bfloat162*>(&u2.x));
            float2 q = __bfloat1622float2(*reinterpret_cast<__nv_bfloat162*>(&u2.y));
            a0 += p.x; a1 += p.y; a2 += q.x; a3 += q.y;
        }
        if (v3) {
            float2 p = __bfloat1622float2(*reinterpret_cast<__nv_bfloat162*>(&u3.x));
            float2 q = __bfloat1622float2(*reinterpret_cast<__nv_bfloat162*>(&u3.y));
            a0 += p.x; a1 += p.y; a2 += q.x; a3 += q.y;
        }
    }
    // self term + bias + relu
    uint2 us = __ldg(&hwb2[(unsigned)node * 16u + fl]);
    float2 ps = __bfloat1622float2(*reinterpret_cast<__nv_bfloat162*>(&us.x));
    float2 qs = __bfloat1622float2(*reinterpret_cast<__nv_bfloat162*>(&us.y));
    float di = g_dinv[node];
    float4 bb = reinterpret_cast<const float4*>(bias)[fl];
    float4 r;
    r.x = fmaxf(di * (a0 + ps.x) + bb.x, 0.f);
    r.y = fmaxf(di * (a1 + ps.y) + bb.y, 0.f);
    r.z = fmaxf(di * (a2 + qs.x) + bb.z, 0.f);
    r.w = fmaxf(di * (a3 + qs.y) + bb.w, 0.f);
    reinterpret_cast<float4*>(g_h)[(unsigned)node * 16u + fl] = r;
}

// ---------------- tensor-core centroid distance + mean pooling + head ----
// per block: 64 node rows x NPAD centroid cols via tf32 mma m16n8k8.
// Last block (atomic ticket) computes the final linear head (k_out folded).
__global__ __launch_bounds__(128) void k_distpool_tc(const float* __restrict__ cent,
                                                     const float* __restrict__ Wout,
                                                     const float* __restrict__ bout,
                                                     float* __restrict__ out) {
    __shared__ uint32_t sH[64][68];
    __shared__ uint32_t sCt[NPAD][68];
    __shared__ float sh2[64];
    __shared__ float sc2[NPAD];
    __shared__ float sPool[NPAD];
    __shared__ unsigned sTicket;
    int t = threadIdx.x;
    int warp = t >> 5, lane = t & 31;
    int grp = lane >> 2, tig = lane & 3;
    int base = blockIdx.x * 64;

    for (int i = t; i < NPAD * 64; i += 128) {
        int col = i >> 6, k = i & 63;
        float v = (col < NCENT) ? cent[col * 64 + k] : 0.f;
        uint32_t b;
        asm("cvt.rna.tf32.f32 %0, %1;" : "=r"(b) : "f"(v));
        sCt[col][k] = b;
    }
    for (int i = t; i < 4096; i += 128) {
        int r = i >> 6, k = i & 63;
        int gn = base + r;
        float v = (gn < NN) ? g_h[(long long)gn * D + k] : 0.f;
        uint32_t b;
        asm("cvt.rna.tf32.f32 %0, %1;" : "=r"(b) : "f"(v));
        sH[r][k] = b;
    }
    if (t < NPAD) sPool[t] = 0.f;
    __syncthreads();

    // per-row |h|^2 (two threads per row)
    {
        int r = t >> 1, half = t & 1;
        float s = 0.f;
        #pragma unroll
        for (int k = 0; k < 32; k++) {
            float x = __uint_as_float(sH[r][half * 32 + k]);
            s += x * x;
        }
        s += __shfl_xor_sync(0xFFFFFFFFu, s, 1);
        if (half == 0) sh2[r] = s;
    }
    if (t < NPAD) {
        float s = 0.f;
        #pragma unroll
        for (int k = 0; k < D; k++) {
            float x = __uint_as_float(sCt[t][k]);
            s += x * x;
        }
        sc2[t] = s;
    }
    __syncthreads();

    float c[13][4];
    #pragma unroll
    for (int nt = 0; nt < 13; nt++)
        #pragma unroll
        for (int j = 0; j < 4; j++) c[nt][j] = 0.f;

    int rowS = warp * 16;
    #pragma unroll
    for (int k0 = 0; k0 < 64; k0 += 8) {
        uint32_t a0 = sH[rowS + grp][k0 + tig];
        uint32_t a1 = sH[rowS + grp + 8][k0 + tig];
        uint32_t a2 = sH[rowS + grp][k0 + tig + 4];
        uint32_t a3 = sH[rowS + grp + 8][k0 + tig + 4];
        #pragma unroll
        for (int nt = 0; nt < 13; nt++) {
            uint32_t b0 = sCt[nt * 8 + grp][k0 + tig];
            uint32_t b1 = sCt[nt * 8 + grp][k0 + tig + 4];
            asm volatile(
                "mma.sync.aligned.m16n8k8.row.col.f32.tf32.tf32.f32 "
                "{%0,%1,%2,%3}, {%4,%5,%6,%7}, {%8,%9}, {%0,%1,%2,%3};"
                : "+f"(c[nt][0]), "+f"(c[nt][1]), "+f"(c[nt][2]), "+f"(c[nt][3])
                : "r"(a0), "r"(a1), "r"(a2), "r"(a3), "r"(b0), "r"(b1));
        }
    }

    int lr0 = rowS + grp, lr1 = lr0 + 8;
    int gr0 = base + lr0, gr1 = base + lr1;
    float h20 = sh2[lr0], h21 = sh2[lr1];
    #pragma unroll
    for (int nt = 0; nt < 13; nt++) {
        int col0 = nt * 8 + tig * 2;
        int col1 = col0 + 1;
        float c20 = sc2[col0], c21 = sc2[col1];
        float d00 = fmaxf(h20 + c20 - 2.f * c[nt][0], 0.f) + EPSV;
        float d01 = fmaxf(h20 + c21 - 2.f * c[nt][1], 0.f) + EPSV;
        float d10 = fmaxf(h21 + c20 - 2.f * c[nt][2], 0.f) + EPSV;
        float d11 = fmaxf(h21 + c21 - 2.f * c[nt][3], 0.f) + EPSV;
        float q00, q01, q10, q11;
        asm("sqrt.approx.f32 %0, %1;" : "=f"(q00) : "f"(d00));
        asm("sqrt.approx.f32 %0, %1;" : "=f"(q01) : "f"(d01));
        asm("sqrt.approx.f32 %0, %1;" : "=f"(q10) : "f"(d10));
        asm("sqrt.approx.f32 %0, %1;" : "=f"(q11) : "f"(d11));
        float s0 = ((gr0 < NN) ? q00 : 0.f) + ((gr1 < NN) ? q10 : 0.f);
        float s1 = ((gr0 < NN) ? q01 : 0.f) + ((gr1 < NN) ? q11 : 0.f);
        #pragma unroll
        for (int m = 4; m < 32; m <<= 1) {
            s0 += __shfl_xor_sync(0xFFFFFFFFu, s0, m);
            s1 += __shfl_xor_sync(0xFFFFFFFFu, s1, m);
        }
        if (lane < 4) {
            if (col0 < NCENT) atomicAdd(&sPool[col0], s0);
            if (col1 < NCENT) atomicAdd(&sPool[col1], s1);
        }
    }
    __syncthreads();
    if (t < NCENT) atomicAdd(&g_pooled[t], sPool[t]);

    // ---- last-block: compute final head (replaces k_out launch) ----
    __threadfence();
    __syncthreads();
    if (t == 0) sTicket = atomicAdd(&g_ticket, 1u);
    __syncthreads();
    if (sTicket == gridDim.x - 1) {
        if (t < NCLS) {
            const float invN = 1.0f / (float)NN;
            float s = 0.f;
            #pragma unroll
            for (int k = 0; k < NCENT; k++) {
                float pv = __ldcg(&g_pooled[k]);   // L2 read: fresh after fences
                s += (pv * invN) * Wout[t * NCENT + k];
            }
            out[t] = s + bout[t];
        }
    }
}

// ---------------- launch ----------------
extern "C" void kernel_launch(void* const* d_in, const int* in_sizes, int n_in,
                              void* d_out, int out_size) {
    const float* x    = (const float*)d_in[0];
    const int*   eiw  = (const int*)d_in[1];     // raw words; dtype detected on device
    const float* We   = (const float*)d_in[2];
    const float* Wg   = (const float*)d_in[3];   // [3,64,64]
    const float* bg   = (const float*)d_in[4];   // [3,64]
    const float* cent = (const float*)d_in[5];   // [100,64]
    const float* Wout = (const float*)d_in[6];   // [10,100]
    const float* bout = (const float*)d_in[7];   // [10]
    float*       out  = (float*)d_out;

    const int edgeBlk  = (NE + 255) / 256;             // 6250
    const int nodeBlk  = (NN + 255) / 256;             // 391
    const int gemmBlk  = (NN + 63) / 64;               // 1563
    const int aggBlk   = (NN / 2 * 32 + 255) / 256;    // 6250 (2 nodes/warp)

    // init (+computeM fused) + CSR/norm build
    k_init<<<nodeBlk, 256>>>(eiw, Wg, We);
    k_degree<<<edgeBlk, 256>>>(eiw);
    k_scan1<<<NSCANBLK, 1024>>>();
    k_scan2<<<1, 128>>>(NSCANBLK);
    k_scan3<<<NSCANBLK, 1024>>>();
    k_fill_csr<<<edgeBlk, 256>>>(eiw);

    // layer 0 (fused): hws = dinv * (x @ M^T)   (tf32 tensor cores, bf16 store)
    k_gemm0_tc<<<gemmBlk, 128>>>(x);
    k_aggregate<<<aggBlk, 256>>>(bg + 0 * D);

    // layer 1
    k_gemm12_tc<<<gemmBlk, 128>>>(Wg + 1 * D * D);
    k_aggregate<<<aggBlk, 256>>>(bg + 1 * D);

    // layer 2
    k_gemm12_tc<<<gemmBlk, 128>>>(Wg + 2 * D * D);
    k_aggregate<<<aggBlk, 256>>>(bg + 2 * D);

    // distance + pooling + head (tensor cores; k_out folded via last-block)
    k_distpool_tc<<<gemmBlk, 128>>>(cent, Wout, bout, out);
}